// round 16
// baseline (speedup 1.0000x reference)
#include <cuda_runtime.h>
#include <math.h>

#define D 64
#define C 128
#define H 512
#define BATCH 4096
#define TM 16
#define NTHREADS 256
#define HS 518          // h1T row stride: conflict-free f32x2 reads
#define STAGE_FLOATS 4096

typedef unsigned long long u64;

__device__ __forceinline__ u64 pack2(float lo, float hi) {
    u64 r; asm("mov.b64 %0, {%1, %2};" : "=l"(r) : "f"(lo), "f"(hi)); return r;
}
__device__ __forceinline__ void fma2(u64& acc, u64 a, u64 b) {
    asm("fma.rn.f32x2 %0, %1, %2, %0;" : "+l"(acc) : "l"(a), "l"(b));
}
__device__ __forceinline__ void unpack2(float& lo, float& hi, u64 v) {
    asm("mov.b64 {%0, %1}, %2;" : "=f"(lo), "=f"(hi) : "l"(v));
}
__device__ __forceinline__ void cp16(unsigned sa, const void* ga) {
    asm volatile("cp.async.cg.shared.global [%0], [%1], 16;" :: "r"(sa), "l"(ga));
}

// Permuted + masked weights (built by prep kernel each launch; idempotent).
__device__ float g_W1p[(D + C) * H];   // [in][p]  in-major, masked, hidden perm
__device__ float g_W2pT[H * H];        // [p][j]   TRANSPOSED masked W2 (j = reduction)
__device__ float g_W3pp[D * H * 2];    // [i][p][2] (mean col i, prescale col D+i), masked
__device__ float g_b1p[H];
__device__ float g_b2p[H];

// Hidden degrees: m_h[k] = (k % 63) + 1. Sorted by degree ascending (ties by k).
__device__ __forceinline__ int permk(int p) {
    if (p < 72) { int d = p / 9; int t = p - 9 * d; return d + 63 * t; }
    int q = p - 72; int d8 = q >> 3; int t = q & 7; return 8 + d8 + 63 * t;
}
__device__ __forceinline__ int degp(int p) {
    return (p < 72) ? (p / 9 + 1) : ((p - 72) / 8 + 9);
}
__device__ __forceinline__ int cntd(int d) {
    return (d <= 0) ? 0 : (d <= 8 ? 9 * d : 8 * d + 8);
}

__global__ void prep_kernel(const float* __restrict__ W1, const float* __restrict__ b1,
                            const float* __restrict__ W2, const float* __restrict__ b2,
                            const float* __restrict__ W3) {
    const int NA = (D + C) * H;
    const int NB = H * H;
    const int NC = D * H;
    const int total = NA + NB + NC + 2 * H;
    for (int idx = blockIdx.x * blockDim.x + threadIdx.x; idx < total;
         idx += gridDim.x * blockDim.x) {
        if (idx < NA) {
            int in = idx >> 9, p = idx & 511;
            float m = (in < D) ? ((degp(p) >= in + 1) ? 1.f : 0.f) : 1.f;
            g_W1p[idx] = W1[in * H + permk(p)] * m;
        } else if (idx < NA + NB) {
            int t = idx - NA;
            int p = t >> 9, j = t & 511;     // TRANSPOSED: [p][j]
            g_W2pT[t] = (degp(p) >= degp(j)) ? W2[permk(j) * H + permk(p)] : 0.f;
        } else if (idx < NA + NB + NC) {
            int t = idx - NA - NB;
            int i = t >> 9, p = t & 511;
            int k = permk(p);
            bool m = (degp(p) <= i);   // m_out = i+1 > deg  <=>  deg <= i
            g_W3pp[t * 2 + 0] = m ? W3[k * (2 * D) + i] : 0.f;
            g_W3pp[t * 2 + 1] = m ? W3[k * (2 * D) + D + i] : 0.f;
        } else {
            int t = idx - NA - NB - NC;
            if (t < H) g_b1p[t] = b1[permk(t)];
            else       g_b2p[t - H] = b2[permk(t - H)];
        }
    }
}

// Partial dot over j range [s,e) (both multiples of 8).
__device__ __forceinline__ float dot_partial(
    const float* __restrict__ hrow, const float* __restrict__ wrow, int s, int e) {
    u64 a0 = 0, a1 = 0, a2 = 0, a3 = 0;
#pragma unroll 2
    for (int j = s; j < e; j += 8) {
        float2 h0 = *(const float2*)&hrow[j];
        float2 h1v = *(const float2*)&hrow[j + 2];
        float2 h2v = *(const float2*)&hrow[j + 4];
        float2 h3 = *(const float2*)&hrow[j + 6];
        float4 wa = *(const float4*)&wrow[j];
        float4 wb = *(const float4*)&wrow[j + 4];
        fma2(a0, pack2(h0.x, h0.y), pack2(wa.x, wa.y));
        fma2(a1, pack2(h1v.x, h1v.y), pack2(wa.z, wa.w));
        fma2(a2, pack2(h2v.x, h2v.y), pack2(wb.x, wb.y));
        fma2(a3, pack2(h3.x, h3.y), pack2(wb.z, wb.w));
    }
    float l0, u0, l1, u1, l2, u2, l3, u3;
    unpack2(l0, u0, a0); unpack2(l1, u1, a1);
    unpack2(l2, u2, a2); unpack2(l3, u3, a3);
    return ((l0 + u0) + (l1 + u1)) + ((l2 + u2) + (l3 + u3));
}

// Dynamic smem layout (floats):
//   h1T[TM][HS]     8288
//   h2s[H][TM]      8192   (ctx overlay during init)
//   stage[4096]            cp.async W2pT tile (cols deg i+1, consumed next step)
//   w3sb[2][1024]   2048   cp.async W3pp row, double-buffered
//   w1s[H]           512   cp.async W1p row i
//   b2s[H]           512
//   epss[TM][D]     1024
//   b3s[2D]          128
//   part[17][32]     544   warp partials (0..7) + per-col combine (8..16)
//   pdot[2][9][16]   288   S1 half partials
#define OF_H2    (TM * HS)
#define OF_STAGE (OF_H2 + H * TM)
#define OF_W3SB  (OF_STAGE + STAGE_FLOATS)
#define OF_W1S   (OF_W3SB + 2048)
#define OF_B2S   (OF_W1S + H)
#define OF_EPS   (OF_B2S + H)
#define OF_B3    (OF_EPS + TM * D)
#define OF_PART  (OF_B3 + 2 * D)
#define OF_PDOT  (OF_PART + 17 * 32)
#define SMEM_FLOATS (OF_PDOT + 288)
#define SMEM_BYTES (SMEM_FLOATS * 4)

__global__ __launch_bounds__(NTHREADS, 2)
void made_main(const float* __restrict__ qc, const float* __restrict__ eps,
               const float* __restrict__ b3g, float* __restrict__ out) {
    extern __shared__ float sm[];
    float* h1T   = sm;                     // [16][518]
    float* h2s   = sm + OF_H2;             // [512][16]
    float* ctx   = h2s;                    // overlay, init only: [128][16]
    float* stage = sm + OF_STAGE;          // [4096]
    float* w3sb  = sm + OF_W3SB;           // [2][1024]
    float* w1s   = sm + OF_W1S;            // [512]
    float* b2s   = sm + OF_B2S;            // [512]
    float* epss  = sm + OF_EPS;            // [16][64]
    float* b3s   = sm + OF_B3;             // [128]
    float* part  = sm + OF_PART;           // [17][32]
    float* pdot  = sm + OF_PDOT;           // [2][9][16]

    const int tid  = threadIdx.x;
    const int r0   = blockIdx.x * TM;
    const int warp = tid >> 5, lane = tid & 31;

    const unsigned stage_sa = (unsigned)__cvta_generic_to_shared(stage);
    const unsigned w3_sa    = (unsigned)__cvta_generic_to_shared(w3sb);
    const unsigned w1_sa    = (unsigned)__cvta_generic_to_shared(w1s);

    // ---- stage ctx (transposed [c][r]), eps rows, b3, b2 ----
    for (int idx = tid; idx < TM * C; idx += NTHREADS) {
        int r = idx >> 7, c = idx & 127;
        ctx[c * TM + r] = qc[(r0 + r) * C + c];
    }
    for (int idx = tid; idx < TM * D; idx += NTHREADS)
        epss[idx] = eps[r0 * D + idx];           // contiguous rows
    for (int idx = tid; idx < 2 * D; idx += NTHREADS)
        b3s[idx] = b3g[idx];
    for (int idx = tid; idx < H; idx += NTHREADS)
        b2s[idx] = __ldg(&g_b2p[idx]);
    __syncthreads();

    // ---- h1_pre init: thread owns hidden unit p, all 16 rows in regs ----
    for (int p = tid; p < H; p += NTHREADS) {
        float acc[TM];
        float b = __ldg(&g_b1p[p]);
#pragma unroll
        for (int r = 0; r < TM; ++r) acc[r] = b;
        for (int c = 0; c < C; ++c) {
            float w = __ldg(&g_W1p[(D + c) * H + p]);
            float4 x0 = *(const float4*)&ctx[c * TM + 0];
            float4 x1 = *(const float4*)&ctx[c * TM + 4];
            float4 x2 = *(const float4*)&ctx[c * TM + 8];
            float4 x3 = *(const float4*)&ctx[c * TM + 12];
            acc[0]  += x0.x * w; acc[1]  += x0.y * w; acc[2]  += x0.z * w; acc[3]  += x0.w * w;
            acc[4]  += x1.x * w; acc[5]  += x1.y * w; acc[6]  += x1.z * w; acc[7]  += x1.w * w;
            acc[8]  += x2.x * w; acc[9]  += x2.y * w; acc[10] += x2.z * w; acc[11] += x2.w * w;
            acc[12] += x3.x * w; acc[13] += x3.y * w; acc[14] += x3.z * w; acc[15] += x3.w * w;
        }
#pragma unroll
        for (int r = 0; r < TM; ++r) h1T[r * HS + p] = acc[r];
    }

    // ---- 64 autoregressive steps ----
    for (int i = 0; i < D; ++i) {
        __syncthreads();   // prev B's h1, stage, w3/w1 prefetches all visible
        const int n2p  = (i > 0) ? cntd(i - 1) : 0;  // established prefix
        const int n2   = cntd(i);                    // cols needed this step
        const int fin  = cntd(i + 1);
        const int ncolp = n2 - n2p;                  // cols dotted in S1 (deg i)
        const int jlimp = (n2 + 7) & ~7;             // pad rows masked-zero

        // ---- prefetch group 0: W1p row i (for S3) + W3pp row i+1 ----
        if (tid < 128)
            cp16(w1_sa + tid * 16, g_W1p + i * H + tid * 4);
        if (i + 1 < D) {
            const int nu = (cntd(i + 1) + 1) >> 1;   // 16B units of 2*fin floats
            const unsigned dst = w3_sa + (((i + 1) & 1) << 12);
            for (int u = tid; u < nu; u += NTHREADS)
                cp16(dst + u * 16, g_W3pp + (size_t)(i + 1) * 1024 + u * 4);
        }
        asm volatile("cp.async.commit_group;");

        // ---- S1: dot cols [n2p, n2) (deg i, h1 inputs already final)
        //          + gather over established cols [0, n2p) ----
        if (ncolp > 0) {
            const int half = tid >> 7;            // 0,1
            const int c = (tid >> 4) & 7;         // 0..7
            const int rr = tid & 15;
            const int jh0 = ((jlimp >> 1) + 7) & ~7;
            const int s = half ? jh0 : 0;
            const int e = half ? jlimp : jh0;
            const float* hrow = h1T + rr * HS;
            pdot[half * 144 + c * TM + rr] =
                dot_partial(hrow, stage + c * jlimp, s, e);
            if (ncolp == 9 && c == 0)
                pdot[half * 144 + 8 * TM + rr] =
                    dot_partial(hrow, stage + 8 * jlimp, s, e);
        }
        {
            const float2* w3cur = (const float2*)(w3sb + ((i & 1) << 10));
            const int pl = tid >> 4, r = tid & 15;
            float mmv = 0.f, ppv = 0.f;
            for (int p = pl; p < n2p; p += 16) {
                float hv = h2s[p * TM + r];
                float2 w3 = w3cur[p];
                mmv += hv * w3.x; ppv += hv * w3.y;
            }
            mmv += __shfl_xor_sync(0xffffffffu, mmv, 16);
            ppv += __shfl_xor_sync(0xffffffffu, ppv, 16);
            if (lane < 16) {
                part[warp * 32 + lane] = mmv;
                part[warp * 32 + 16 + lane] = ppv;
            }
        }
        __syncthreads();   // pdot + part visible

        // ---- S2: combine new cols -> h2s + per-col part; stage refill ----
        if (i + 1 < D) {   // prefetch W2pT cols [n2, fin) for NEXT step's S1
            const int ncoln = fin - n2;
            const int jlimn = (fin + 7) & ~7;
            const int nunit = (ncoln * jlimn) >> 2;
            const int upr = jlimn >> 2;
            for (int u = tid; u < nunit; u += NTHREADS) {
                int c = u / upr, jo = (u - c * upr) << 2;
                cp16(stage_sa + ((c * jlimn + jo) << 2),
                     g_W2pT + (size_t)(n2 + c) * H + jo);
            }
        }
        asm volatile("cp.async.commit_group;");
        if (tid < ncolp * TM) {
            const float2* w3cur = (const float2*)(w3sb + ((i & 1) << 10));
            const int c = tid >> 4, r = tid & 15;
            const int p = n2p + c;
            float hv = fmaxf(pdot[c * TM + r] + pdot[144 + c * TM + r]
                             + b2s[p], 0.f);
            h2s[p * TM + r] = hv;
            float2 w3 = w3cur[p];
            part[(8 + c) * 32 + r] = hv * w3.x;
            part[(8 + c) * 32 + 16 + r] = hv * w3.y;
        }
        asm volatile("cp.async.wait_group 1;");   // group 0 landed (w1s ready)
        __syncthreads();   // part complete + w1s visible

        // ---- S3: z per warp (broadcast part reads), out, h1 update ----
        const int ra = warp * 2, rb = ra + 1;
        const int kmax = 8 + ncolp;
        float mmA = b3s[i], ppA = b3s[D + i];
        float mmB = mmA, ppB = ppA;
        for (int k = 0; k < kmax; ++k) {
            mmA += part[k * 32 + ra];  ppA += part[k * 32 + 16 + ra];
            mmB += part[k * 32 + rb];  ppB += part[k * 32 + 16 + rb];
        }
        float spA = fmaxf(ppA, 0.f) + log1pf(expf(-fabsf(ppA)));
        float spB = fmaxf(ppB, 0.f) + log1pf(expf(-fabsf(ppB)));
        float za = mmA + spA * epss[ra * D + i];
        float zb = mmB + spB * epss[rb * D + i];
        if (lane == 0) out[(r0 + ra) * D + i] = za;
        if (lane == 1) out[(r0 + rb) * D + i] = zb;

        // rank-1 h1 update: rows [n2, H), relu rows < fin (finalized)
        for (int p = n2 + lane; p < H; p += 32) {
            float wv = w1s[p];
            float va = h1T[ra * HS + p] + za * wv;
            float vb = h1T[rb * HS + p] + zb * wv;
            if (p < fin) { va = fmaxf(va, 0.f); vb = fmaxf(vb, 0.f); }
            h1T[ra * HS + p] = va;
            h1T[rb * HS + p] = vb;
        }
        asm volatile("cp.async.wait_group 0;");   // stage landed (own copies)
        // top-of-loop barrier publishes h1/stage/pdot/h2s for next step
    }
}

extern "C" void kernel_launch(void* const* d_in, const int* in_sizes, int n_in,
                              void* d_out, int out_size) {
    const float* q   = (const float*)d_in[0];  // (4096, 128)
    const float* eps = (const float*)d_in[1];  // (4096, 64)
    const float* W1  = (const float*)d_in[2];  // (192, 512)
    const float* b1  = (const float*)d_in[3];  // (512,)
    const float* W2  = (const float*)d_in[4];  // (512, 512)
    const float* b2  = (const float*)d_in[5];  // (512,)
    const float* W3  = (const float*)d_in[6];  // (512, 128)
    const float* b3  = (const float*)d_in[7];  // (128,)
    float* out = (float*)d_out;                // (4096, 64)

    cudaFuncSetAttribute(made_main, cudaFuncAttributeMaxDynamicSharedMemorySize,
                         SMEM_BYTES);

    prep_kernel<<<408, 256>>>(W1, b1, W2, b2, W3);
    made_main<<<BATCH / TM, NTHREADS, SMEM_BYTES>>>(q, eps, b3, out);
}

// round 17
// speedup vs baseline: 1.0595x; 1.0595x over previous
#include <cuda_runtime.h>
#include <math.h>

#define D 64
#define C 128
#define H 512
#define BATCH 4096
#define TM 16
#define NTHREADS 256
#define HS 518          // h1T row stride: conflict-free f32x2 reads
#define STAGE_FLOATS 4096

typedef unsigned long long u64;

__device__ __forceinline__ u64 pack2(float lo, float hi) {
    u64 r; asm("mov.b64 %0, {%1, %2};" : "=l"(r) : "f"(lo), "f"(hi)); return r;
}
__device__ __forceinline__ void fma2(u64& acc, u64 a, u64 b) {
    asm("fma.rn.f32x2 %0, %1, %2, %0;" : "+l"(acc) : "l"(a), "l"(b));
}
__device__ __forceinline__ void unpack2(float& lo, float& hi, u64 v) {
    asm("mov.b64 {%0, %1}, %2;" : "=f"(lo), "=f"(hi) : "l"(v));
}
__device__ __forceinline__ void cp16(unsigned sa, const void* ga) {
    asm volatile("cp.async.cg.shared.global [%0], [%1], 16;" :: "r"(sa), "l"(ga));
}

// Permuted + masked weights (built by prep kernel each launch; idempotent).
__device__ float g_W1p[(D + C) * H];   // [in][p]  in-major, masked, hidden perm
__device__ float g_W2pT[H * H];        // [p][j]   TRANSPOSED masked W2 (j = reduction)
__device__ float g_W3pp[D * H * 2];    // [i][p][2] (mean col i, prescale col D+i), masked
__device__ float g_b1p[H];
__device__ float g_b2p[H];

// Hidden degrees: m_h[k] = (k % 63) + 1. Sorted by degree ascending (ties by k).
__device__ __forceinline__ int permk(int p) {
    if (p < 72) { int d = p / 9; int t = p - 9 * d; return d + 63 * t; }
    int q = p - 72; int d8 = q >> 3; int t = q & 7; return 8 + d8 + 63 * t;
}
__device__ __forceinline__ int degp(int p) {
    return (p < 72) ? (p / 9 + 1) : ((p - 72) / 8 + 9);
}
__device__ __forceinline__ int cntd(int d) {
    return (d <= 0) ? 0 : (d <= 8 ? 9 * d : 8 * d + 8);
}

__global__ void prep_kernel(const float* __restrict__ W1, const float* __restrict__ b1,
                            const float* __restrict__ W2, const float* __restrict__ b2,
                            const float* __restrict__ W3) {
    const int NA = (D + C) * H;
    const int NB = H * H;
    const int NC = D * H;
    const int total = NA + NB + NC + 2 * H;
    for (int idx = blockIdx.x * blockDim.x + threadIdx.x; idx < total;
         idx += gridDim.x * blockDim.x) {
        if (idx < NA) {
            int in = idx >> 9, p = idx & 511;
            float m = (in < D) ? ((degp(p) >= in + 1) ? 1.f : 0.f) : 1.f;
            g_W1p[idx] = W1[in * H + permk(p)] * m;
        } else if (idx < NA + NB) {
            int t = idx - NA;
            int p = t >> 9, j = t & 511;     // TRANSPOSED: [p][j]
            g_W2pT[t] = (degp(p) >= degp(j)) ? W2[permk(j) * H + permk(p)] : 0.f;
        } else if (idx < NA + NB + NC) {
            int t = idx - NA - NB;
            int i = t >> 9, p = t & 511;
            int k = permk(p);
            bool m = (degp(p) <= i);   // m_out = i+1 > deg  <=>  deg <= i
            g_W3pp[t * 2 + 0] = m ? W3[k * (2 * D) + i] : 0.f;
            g_W3pp[t * 2 + 1] = m ? W3[k * (2 * D) + D + i] : 0.f;
        } else {
            int t = idx - NA - NB - NC;
            if (t < H) g_b1p[t] = b1[permk(t)];
            else       g_b2p[t - H] = b2[permk(t - H)];
        }
    }
}

// Column dot over j in [s,e) (multiples of 8), inline h1 update for j >= n2
// (value relu'd in registers; rows [fin,jlim) hit masked-zero weights).
__device__ __forceinline__ float dot_col(
    const float* __restrict__ h1row, const float* __restrict__ wrow,
    const float* __restrict__ w1cur, int s, int e, int n2, float zr) {
    u64 a0 = 0, a1 = 0, a2 = 0, a3 = 0;
    const int pe0 = n2 & ~7;
    const int pe = pe0 < e ? pe0 : e;
    int j = s;
#pragma unroll 2
    for (; j < pe; j += 8) {
        float2 h0 = *(const float2*)&h1row[j];
        float2 h1v = *(const float2*)&h1row[j + 2];
        float2 h2v = *(const float2*)&h1row[j + 4];
        float2 h3 = *(const float2*)&h1row[j + 6];
        float4 wa = *(const float4*)&wrow[j];
        float4 wb = *(const float4*)&wrow[j + 4];
        fma2(a0, pack2(h0.x, h0.y), pack2(wa.x, wa.y));
        fma2(a1, pack2(h1v.x, h1v.y), pack2(wa.z, wa.w));
        fma2(a2, pack2(h2v.x, h2v.y), pack2(wb.x, wb.y));
        fma2(a3, pack2(h3.x, h3.y), pack2(wb.z, wb.w));
    }
    for (; j < e; j += 8) {
        float hv[8];
#pragma unroll
        for (int k = 0; k < 8; ++k) {
            float x = h1row[j + k];
            if (j + k >= n2) x = fmaxf(x + zr * w1cur[j + k], 0.f);
            hv[k] = x;
        }
        float4 wa = *(const float4*)&wrow[j];
        float4 wb = *(const float4*)&wrow[j + 4];
        fma2(a0, pack2(hv[0], hv[1]), pack2(wa.x, wa.y));
        fma2(a1, pack2(hv[2], hv[3]), pack2(wa.z, wa.w));
        fma2(a2, pack2(hv[4], hv[5]), pack2(wb.x, wb.y));
        fma2(a3, pack2(hv[6], hv[7]), pack2(wb.z, wb.w));
    }
    float l0, u0, l1, u1, l2, u2, l3, u3;
    unpack2(l0, u0, a0); unpack2(l1, u1, a1);
    unpack2(l2, u2, a2); unpack2(l3, u3, a3);
    return ((l0 + u0) + (l1 + u1)) + ((l2 + u2) + (l3 + u3));
}

// Dynamic smem layout (floats):
//   h1T[TM][HS]     8288
//   h2s[H][TM]      8192   (ctx overlay during init)
//   stage[4096]            cp.async W2pT tile for this step's dot
//   w3sb[2][1024]   2048   cp.async W3pp row, double-buffered
//   w1sb[2][512]    1024   cp.async W1p row, double-buffered (lazy persist)
//   b2s[H]           512
//   epss[TM][D]     1024
//   b3s[2D]          128
//   part[8][32]      256   per-warp gather partials
//   pdot[2][9][16]   288   dot half partials (combined next step)
//   zsh[16]           16   z of this step (consumed next step's persist)
#define OF_H2    (TM * HS)
#define OF_STAGE (OF_H2 + H * TM)
#define OF_W3SB  (OF_STAGE + STAGE_FLOATS)
#define OF_W1SB  (OF_W3SB + 2048)
#define OF_B2S   (OF_W1SB + 1024)
#define OF_EPS   (OF_B2S + H)
#define OF_B3    (OF_EPS + TM * D)
#define OF_PART  (OF_B3 + 2 * D)
#define OF_PDOT  (OF_PART + 256)
#define OF_ZSH   (OF_PDOT + 288)
#define SMEM_FLOATS (OF_ZSH + TM)
#define SMEM_BYTES (SMEM_FLOATS * 4)

__global__ __launch_bounds__(NTHREADS, 2)
void made_main(const float* __restrict__ qc, const float* __restrict__ eps,
               const float* __restrict__ b3g, float* __restrict__ out) {
    extern __shared__ float sm[];
    float* h1T   = sm;                     // [16][518]
    float* h2s   = sm + OF_H2;             // [512][16]
    float* ctx   = h2s;                    // overlay, init only: [128][16]
    float* stage = sm + OF_STAGE;          // [4096]
    float* w3sb  = sm + OF_W3SB;           // [2][1024]
    float* w1sb  = sm + OF_W1SB;           // [2][512]
    float* b2s   = sm + OF_B2S;            // [512]
    float* epss  = sm + OF_EPS;            // [16][64]
    float* b3s   = sm + OF_B3;             // [128]
    float* part  = sm + OF_PART;           // [8][32]
    float* pdot  = sm + OF_PDOT;           // [2][9][16]
    float* zsh   = sm + OF_ZSH;            // [16]

    const int tid  = threadIdx.x;
    const int r0   = blockIdx.x * TM;
    const int warp = tid >> 5, lane = tid & 31;
    const int r    = tid & 15;
    const int pl   = tid >> 4;             // 0..15

    const unsigned sa = (unsigned)__cvta_generic_to_shared(sm);
    const unsigned stage_sa = sa + OF_STAGE * 4;
    const unsigned w3_sa    = sa + OF_W3SB * 4;
    const unsigned w1_sa    = sa + OF_W1SB * 4;

    // ---- stage ctx (transposed [c][r]), eps rows, b3, b2 ----
    for (int idx = tid; idx < TM * C; idx += NTHREADS) {
        int rr = idx >> 7, c = idx & 127;
        ctx[c * TM + rr] = qc[(r0 + rr) * C + c];
    }
    for (int idx = tid; idx < TM * D; idx += NTHREADS)
        epss[idx] = eps[r0 * D + idx];           // contiguous rows
    for (int idx = tid; idx < 2 * D; idx += NTHREADS)
        b3s[idx] = b3g[idx];
    for (int idx = tid; idx < H; idx += NTHREADS)
        b2s[idx] = __ldg(&g_b2p[idx]);
    __syncthreads();

    // ---- h1_pre init: thread owns hidden unit p, all 16 rows in regs ----
    for (int p = tid; p < H; p += NTHREADS) {
        float acc[TM];
        float b = __ldg(&g_b1p[p]);
#pragma unroll
        for (int rr = 0; rr < TM; ++rr) acc[rr] = b;
        for (int c = 0; c < C; ++c) {
            float w = __ldg(&g_W1p[(D + c) * H + p]);
            float4 x0 = *(const float4*)&ctx[c * TM + 0];
            float4 x1 = *(const float4*)&ctx[c * TM + 4];
            float4 x2 = *(const float4*)&ctx[c * TM + 8];
            float4 x3 = *(const float4*)&ctx[c * TM + 12];
            acc[0]  += x0.x * w; acc[1]  += x0.y * w; acc[2]  += x0.z * w; acc[3]  += x0.w * w;
            acc[4]  += x1.x * w; acc[5]  += x1.y * w; acc[6]  += x1.z * w; acc[7]  += x1.w * w;
            acc[8]  += x2.x * w; acc[9]  += x2.y * w; acc[10] += x2.z * w; acc[11] += x2.w * w;
            acc[12] += x3.x * w; acc[13] += x3.y * w; acc[14] += x3.z * w; acc[15] += x3.w * w;
        }
#pragma unroll
        for (int rr = 0; rr < TM; ++rr) h1T[rr * HS + p] = acc[rr];
    }

    // ---- 64 autoregressive steps (2 barriers each) ----
    for (int i = 0; i < D; ++i) {
        __syncthreads();   // T: prev dot/suffix h1, pdot, zsh, prefetches visible
        const int n2p  = (i > 0) ? cntd(i - 1) : 0;  // established prefix
        const int n2   = cntd(i);
        const int fin  = cntd(i + 1);
        const int ncol = fin - n2;                 // dot cols (8/9; 0 at i=63)
        const int jlim = (fin + 7) & ~7;

        // ---- prefetch group 0: W1p row i (dbuf) + W3pp row i+1 ----
        if (tid < 128)
            cp16(w1_sa + ((i & 1) << 11) + tid * 16, g_W1p + i * H + tid * 4);
        if (i + 1 < D) {
            const int nu = (cntd(i + 1) + 1) >> 1;
            const unsigned dst = w3_sa + (((i + 1) & 1) << 12);
            for (int u = tid; u < nu; u += NTHREADS)
                cp16(dst + u * 16, g_W3pp + (size_t)(i + 1) * 1024 + u * 4);
        }
        asm volatile("cp.async.commit_group;");
        // ---- group 1: W2pT tile cols [n2, fin) for THIS step's dot ----
        if (ncol > 0) {
            const int nunit = (ncol * jlim) >> 2;
            const int upr = jlim >> 2;
            for (int u = tid; u < nunit; u += NTHREADS) {
                int c = u / upr, jo = (u - c * upr) << 2;
                cp16(stage_sa + ((c * jlim + jo) << 2),
                     g_W2pT + (size_t)(n2 + c) * H + jo);
            }
        }
        asm volatile("cp.async.commit_group;");

        // ---- Phase A: lazy persist + gather + combine -> part ----
        {
            const float2* w3cur = (const float2*)(w3sb + ((i & 1) << 10));
            const float* w1prev = w1sb + (((i & 1) ^ 1) << 9);
            float mmv = 0.f, ppv = 0.f;
            for (int p = pl; p < n2p; p += 16) {
                float hv = h2s[p * TM + r];
                float2 w3 = w3cur[p];
                mmv += hv * w3.x; ppv += hv * w3.y;
            }
            {   // pending rows/cols [n2p, n2): persist h1 (z from prev step),
                // combine pdot -> h2s, include in gather
                int p0 = n2p + ((pl - n2p) & 15);
                for (int p = p0; p < n2; p += 16) {
                    int c = p - n2p;
                    h1T[r * HS + p] =
                        fmaxf(h1T[r * HS + p] + zsh[r] * w1prev[p], 0.f);
                    float hv = fmaxf(pdot[c * TM + r] + pdot[144 + c * TM + r]
                                     + b2s[p], 0.f);
                    h2s[p * TM + r] = hv;
                    float2 w3 = w3cur[p];
                    mmv += hv * w3.x; ppv += hv * w3.y;
                }
            }
            mmv += __shfl_xor_sync(0xffffffffu, mmv, 16);
            ppv += __shfl_xor_sync(0xffffffffu, ppv, 16);
            if (lane < 16) {
                part[warp * 32 + lane] = mmv;
                part[warp * 32 + 16 + lane] = ppv;
            }
        }
        asm volatile("cp.async.wait_group 0;");   // both groups landed
        __syncthreads();   // M: part, persisted h1, w1s, stage visible

        // ---- Phase ZCB (no further barriers this step) ----
        const float* w1cur = w1sb + ((i & 1) << 9);
        // z for this thread's row r (8-term sums over part)
        float mm = b3s[i], pp = b3s[D + i];
#pragma unroll
        for (int k = 0; k < 8; ++k) {
            mm += part[k * 32 + r];
            pp += part[k * 32 + 16 + r];
        }
        float sp = fmaxf(pp, 0.f) + log1pf(expf(-fabsf(pp)));
        float z_rr = mm + sp * epss[r * D + i];
        if (warp == 0 && lane < 16) {
            out[(r0 + r) * D + i] = z_rr;
            zsh[r] = z_rr;           // ordered vs A-readers by barrier M/T
        }

        // dot for cols [n2, fin), inline h1 update for rows [n2, fin)
        if (ncol > 0) {
            const int half = tid >> 7;
            const int c = (tid >> 4) & 7;
            const int jh0 = ((jlim >> 1) + 7) & ~7;
            const int s = half ? jh0 : 0;
            const int e = half ? jlim : jh0;
            const float* hrow = h1T + r * HS;
            pdot[half * 144 + c * TM + r] =
                dot_col(hrow, stage + c * jlim, w1cur, s, e, n2, z_rr);
            if (ncol == 9 && c == 0)
                pdot[half * 144 + 8 * TM + r] =
                    dot_col(hrow, stage + 8 * jlim, w1cur, s, e, n2, z_rr);
        }

        // suffix h1 update rows [fin, H) (disjoint from dot reads; no relu —
        // applied at each row's finalizing persist)
        {
            const int ra = warp * 2, rb = ra + 1;
            float zA = __shfl_sync(0xffffffffu, z_rr, ra);
            float zB = __shfl_sync(0xffffffffu, z_rr, rb);
            for (int p = fin + lane; p < H; p += 32) {
                float wv = w1cur[p];
                h1T[ra * HS + p] += zA * wv;
                h1T[rb * HS + p] += zB * wv;
            }
        }
        // top-of-loop barrier publishes everything for next step
    }
}

extern "C" void kernel_launch(void* const* d_in, const int* in_sizes, int n_in,
                              void* d_out, int out_size) {
    const float* q   = (const float*)d_in[0];  // (4096, 128)
    const float* eps = (const float*)d_in[1];  // (4096, 64)
    const float* W1  = (const float*)d_in[2];  // (192, 512)
    const float* b1  = (const float*)d_in[3];  // (512,)
    const float* W2  = (const float*)d_in[4];  // (512, 512)
    const float* b2  = (const float*)d_in[5];  // (512,)
    const float* W3  = (const float*)d_in[6];  // (512, 128)
    const float* b3  = (const float*)d_in[7];  // (128,)
    float* out = (float*)d_out;                // (4096, 64)

    cudaFuncSetAttribute(made_main, cudaFuncAttributeMaxDynamicSharedMemorySize,
                         SMEM_BYTES);

    prep_kernel<<<408, 256>>>(W1, b1, W2, b2, W3);
    made_main<<<BATCH / TM, NTHREADS, SMEM_BYTES>>>(q, eps, b3, out);
}